// round 4
// baseline (speedup 1.0000x reference)
#include <cuda_runtime.h>

#define B  8
#define D  512
#define T  8192
#define CS 16
#define TC 512   // T / CS
#define DH 64    // D / 8

// Scratch (no cudaMalloc allowed)
__device__ float g_pooled[B * D * TC];          // 8 MiB (L2-resident)
__device__ float g_gate[B * D * TC];            // 8 MiB (L2-resident)

// ---------------------------------------------------------------------------
// Kernel 1: per (b,d) row — chunk sums of 16, inclusive scan, divide by count.
// Coalesced block-stride float4 loads (streaming), lane-group-of-4 reduction,
// 512-wide block scan.
// ---------------------------------------------------------------------------
__global__ void pool_kernel(const float* __restrict__ x) {
    int row = blockIdx.x;                      // b*D + d
    const float4* xr = reinterpret_cast<const float4*>(x) + (size_t)row * (T / 4);
    int j = threadIdx.x;

    __shared__ float csum[TC];
    __shared__ float wsum[16];

    // Front-batched coalesced streaming loads (MLP=4, no L2 pollution)
    float4 f0 = __ldcs(&xr[j]);
    float4 f1 = __ldcs(&xr[j + 512]);
    float4 f2 = __ldcs(&xr[j + 1024]);
    float4 f3 = __ldcs(&xr[j + 1536]);

    float s0 = (f0.x + f0.y) + (f0.z + f0.w);
    float s1 = (f1.x + f1.y) + (f1.z + f1.w);
    float s2 = (f2.x + f2.y) + (f2.z + f2.w);
    float s3 = (f3.x + f3.y) + (f3.z + f3.w);

    s0 += __shfl_xor_sync(0xffffffffu, s0, 1);
    s0 += __shfl_xor_sync(0xffffffffu, s0, 2);
    s1 += __shfl_xor_sync(0xffffffffu, s1, 1);
    s1 += __shfl_xor_sync(0xffffffffu, s1, 2);
    s2 += __shfl_xor_sync(0xffffffffu, s2, 1);
    s2 += __shfl_xor_sync(0xffffffffu, s2, 2);
    s3 += __shfl_xor_sync(0xffffffffu, s3, 1);
    s3 += __shfl_xor_sync(0xffffffffu, s3, 2);

    if ((j & 3) == 0) {
        int c = j >> 2;
        csum[c +   0] = s0;
        csum[c + 128] = s1;
        csum[c + 256] = s2;
        csum[c + 384] = s3;
    }
    __syncthreads();

    int lane = j & 31, warp = j >> 5;
    float v = csum[j];
    #pragma unroll
    for (int off = 1; off < 32; off <<= 1) {
        float n = __shfl_up_sync(0xffffffffu, v, off);
        if (lane >= off) v += n;
    }
    if (lane == 31) wsum[warp] = v;
    __syncthreads();
    if (warp == 0) {
        float w = (lane < 16) ? wsum[lane] : 0.f;
        #pragma unroll
        for (int off = 1; off < 16; off <<= 1) {
            float n = __shfl_up_sync(0xffffffffu, w, off);
            if (lane >= off) w += n;
        }
        if (lane < 16) wsum[lane] = w;
    }
    __syncthreads();

    float prefix = (warp > 0) ? wsum[warp - 1] : 0.f;
    float total  = v + prefix;
    g_pooled[(size_t)row * TC + j] = total / (float)(CS * (j + 1));
}

// ---------------------------------------------------------------------------
// Kernel 2: fused MLP.  Per CTA: b = blockIdx.y, t-tile of 32 (blockIdx.x).
// Phase 1: h[64][32] = relu(w1 @ pooled + b1)   (K=512, 4 d-chunks of 128)
// Phase 2: g[512][32] = sigmoid(w2 @ h + b2)    (4 o-chunks of 128)
// 256 threads. No global intermediates.
// SMEM ORDER MATTERS: float4-accessed arrays (Ps, Hs) first so they stay
// 16B-aligned; Ws (scalar access only) last, padded to 16B multiple.
// ---------------------------------------------------------------------------
__global__ void __launch_bounds__(256) mlp_kernel(
        const float* __restrict__ w1, const float* __restrict__ b1,
        const float* __restrict__ w2, const float* __restrict__ b2) {
    __shared__ __align__(16) float Ps[128 * 32];   // [d_local][t] 16 KiB
    __shared__ __align__(16) float Hs[64 * 32];    // [k][t] 8 KiB
    __shared__ __align__(16) float Ws[128 * 65 + 4]; // W1 [64][129] / W2 [128][65]

    int tid  = threadIdx.x;
    int t0   = blockIdx.x * 32;
    int b    = blockIdx.y;
    int tq   = tid & 7;                // t-quad: t = tq*4 .. tq*4+3
    int og   = tid >> 3;               // 0..31

    // ---- Phase 1: h = w1 @ pooled (each thread: 2 o x 4 t) ----
    float hacc[2][4];
    #pragma unroll
    for (int o = 0; o < 2; o++)
        #pragma unroll
        for (int q = 0; q < 4; q++) hacc[o][q] = 0.f;

    for (int dc = 0; dc < D; dc += 128) {
        // load pooled chunk [128 d][32 t]
        for (int i = tid; i < 128 * 32; i += 256) {
            int d = i >> 5, t = i & 31;
            Ps[i] = g_pooled[((size_t)(b * D) + dc + d) * TC + t0 + t];
        }
        // load w1 chunk [64 o][128 d], padded stride 129
        for (int i = tid; i < 64 * 128; i += 256) {
            int o = i >> 7, d = i & 127;
            Ws[o * 129 + d] = w1[o * D + dc + d];
        }
        __syncthreads();

        #pragma unroll 4
        for (int dd = 0; dd < 128; dd++) {
            float4 p = *reinterpret_cast<const float4*>(&Ps[dd * 32 + tq * 4]);
            float w0 = Ws[(og * 2 + 0) * 129 + dd];
            float w1v = Ws[(og * 2 + 1) * 129 + dd];
            hacc[0][0] = fmaf(w0, p.x, hacc[0][0]);
            hacc[0][1] = fmaf(w0, p.y, hacc[0][1]);
            hacc[0][2] = fmaf(w0, p.z, hacc[0][2]);
            hacc[0][3] = fmaf(w0, p.w, hacc[0][3]);
            hacc[1][0] = fmaf(w1v, p.x, hacc[1][0]);
            hacc[1][1] = fmaf(w1v, p.y, hacc[1][1]);
            hacc[1][2] = fmaf(w1v, p.z, hacc[1][2]);
            hacc[1][3] = fmaf(w1v, p.w, hacc[1][3]);
        }
        __syncthreads();
    }

    // bias + relu -> Hs[o][t]
    #pragma unroll
    for (int o = 0; o < 2; o++) {
        int oo = og * 2 + o;
        float bb = b1[oo];
        float4 hv;
        hv.x = fmaxf(hacc[o][0] + bb, 0.f);
        hv.y = fmaxf(hacc[o][1] + bb, 0.f);
        hv.z = fmaxf(hacc[o][2] + bb, 0.f);
        hv.w = fmaxf(hacc[o][3] + bb, 0.f);
        *reinterpret_cast<float4*>(&Hs[oo * 32 + tq * 4]) = hv;
    }
    __syncthreads();

    // ---- Phase 2: g = sigmoid(w2 @ h + b2), 4 o-chunks of 128 ----
    for (int oc = 0; oc < D; oc += 128) {
        // load w2 chunk [128 o][64 k], padded stride 65
        for (int i = tid; i < 128 * 64; i += 256) {
            int o = i >> 6, k = i & 63;
            Ws[o * 65 + k] = w2[(oc + o) * DH + k];
        }
        __syncthreads();

        float acc[4][4];
        #pragma unroll
        for (int o = 0; o < 4; o++)
            #pragma unroll
            for (int q = 0; q < 4; q++) acc[o][q] = 0.f;

        #pragma unroll 4
        for (int k = 0; k < 64; k++) {
            float4 h = *reinterpret_cast<const float4*>(&Hs[k * 32 + tq * 4]);
            #pragma unroll
            for (int o = 0; o < 4; o++) {
                float w = Ws[(og * 4 + o) * 65 + k];
                acc[o][0] = fmaf(w, h.x, acc[o][0]);
                acc[o][1] = fmaf(w, h.y, acc[o][1]);
                acc[o][2] = fmaf(w, h.z, acc[o][2]);
                acc[o][3] = fmaf(w, h.w, acc[o][3]);
            }
        }

        #pragma unroll
        for (int o = 0; o < 4; o++) {
            int oo = oc + og * 4 + o;
            float bb = b2[oo];
            float4 g;
            g.x = 1.f / (1.f + __expf(-(acc[o][0] + bb)));
            g.y = 1.f / (1.f + __expf(-(acc[o][1] + bb)));
            g.z = 1.f / (1.f + __expf(-(acc[o][2] + bb)));
            g.w = 1.f / (1.f + __expf(-(acc[o][3] + bb)));
            *reinterpret_cast<float4*>(
                &g_gate[((size_t)(b * D) + oo) * TC + t0 + tq * 4]) = g;
        }
        __syncthreads();
    }
}

// ---------------------------------------------------------------------------
// Kernel 3: out = repeat(g,16) * x. Coalesced float4, 4-way ILP, streaming x.
// ---------------------------------------------------------------------------
__global__ void scale_kernel(const float* __restrict__ x, float* __restrict__ out) {
    const float4* x4 = reinterpret_cast<const float4*>(x);
    float4* o4 = reinterpret_cast<float4*>(out);
    size_t base = (size_t)blockIdx.x * blockDim.x + threadIdx.x;
    const size_t stride = (size_t)gridDim.x * blockDim.x;

    float4 xv[4];
    float  g[4];
    #pragma unroll
    for (int k = 0; k < 4; k++) {
        size_t i = base + (size_t)k * stride;
        xv[k] = __ldcs(&x4[i]);
    }
    #pragma unroll
    for (int k = 0; k < 4; k++) {
        size_t i = base + (size_t)k * stride;
        size_t row = i >> 11;               // / (T/4)
        size_t c   = (i & 2047) >> 2;       // chunk index
        g[k] = g_gate[row * TC + c];
    }
    #pragma unroll
    for (int k = 0; k < 4; k++) {
        size_t i = base + (size_t)k * stride;
        o4[i] = make_float4(xv[k].x * g[k], xv[k].y * g[k],
                            xv[k].z * g[k], xv[k].w * g[k]);
    }
}

// ---------------------------------------------------------------------------
extern "C" void kernel_launch(void* const* d_in, const int* in_sizes, int n_in,
                              void* d_out, int out_size) {
    const float* x  = (const float*)d_in[0];
    const float* w1 = (const float*)d_in[1];
    const float* b1 = (const float*)d_in[2];
    const float* w2 = (const float*)d_in[3];
    const float* b2 = (const float*)d_in[4];
    float* out = (float*)d_out;

    pool_kernel<<<B * D, 512>>>(x);
    mlp_kernel<<<dim3(16, B), 256>>>(w1, b1, w2, b2);
    scale_kernel<<<8192, 256>>>(x, out);
}

// round 5
// speedup vs baseline: 1.4428x; 1.4428x over previous
#include <cuda_runtime.h>

#define B  8
#define D  512
#define T  8192
#define CS 16
#define TC 512   // T / CS
#define DH 64    // D / 8

// Scratch (no cudaMalloc allowed)
__device__ float g_pooled[B * D * TC];          // 8 MiB
__device__ float g_hpart[4][B * DH * TC];       // 1 MiB per split-K slice
__device__ float g_gate[B * D * TC];            // 8 MiB

// ---------------------------------------------------------------------------
// Kernel 1: per (b,d) row — chunk sums of 16, inclusive scan, divide by count.
// Coalesced block-stride float4 streaming loads, lane-group-of-4 reduction,
// 512-wide block scan. Measured 24 us (~DRAM floor).
// ---------------------------------------------------------------------------
__global__ void pool_kernel(const float* __restrict__ x) {
    int row = blockIdx.x;                      // b*D + d
    const float4* xr = reinterpret_cast<const float4*>(x) + (size_t)row * (T / 4);
    int j = threadIdx.x;

    __shared__ float csum[TC];
    __shared__ float wsum[16];

    float4 f0 = __ldcs(&xr[j]);
    float4 f1 = __ldcs(&xr[j + 512]);
    float4 f2 = __ldcs(&xr[j + 1024]);
    float4 f3 = __ldcs(&xr[j + 1536]);

    float s0 = (f0.x + f0.y) + (f0.z + f0.w);
    float s1 = (f1.x + f1.y) + (f1.z + f1.w);
    float s2 = (f2.x + f2.y) + (f2.z + f2.w);
    float s3 = (f3.x + f3.y) + (f3.z + f3.w);

    s0 += __shfl_xor_sync(0xffffffffu, s0, 1);
    s0 += __shfl_xor_sync(0xffffffffu, s0, 2);
    s1 += __shfl_xor_sync(0xffffffffu, s1, 1);
    s1 += __shfl_xor_sync(0xffffffffu, s1, 2);
    s2 += __shfl_xor_sync(0xffffffffu, s2, 1);
    s2 += __shfl_xor_sync(0xffffffffu, s2, 2);
    s3 += __shfl_xor_sync(0xffffffffu, s3, 1);
    s3 += __shfl_xor_sync(0xffffffffu, s3, 2);

    if ((j & 3) == 0) {
        int c = j >> 2;
        csum[c +   0] = s0;
        csum[c + 128] = s1;
        csum[c + 256] = s2;
        csum[c + 384] = s3;
    }
    __syncthreads();

    int lane = j & 31, warp = j >> 5;
    float v = csum[j];
    #pragma unroll
    for (int off = 1; off < 32; off <<= 1) {
        float n = __shfl_up_sync(0xffffffffu, v, off);
        if (lane >= off) v += n;
    }
    if (lane == 31) wsum[warp] = v;
    __syncthreads();
    if (warp == 0) {
        float w = (lane < 16) ? wsum[lane] : 0.f;
        #pragma unroll
        for (int off = 1; off < 16; off <<= 1) {
            float n = __shfl_up_sync(0xffffffffu, w, off);
            if (lane >= off) w += n;
        }
        if (lane < 16) wsum[lane] = w;
    }
    __syncthreads();

    float prefix = (warp > 0) ? wsum[warp - 1] : 0.f;
    float total  = v + prefix;
    g_pooled[(size_t)row * TC + j] = total / (float)(CS * (j + 1));
}

// ---------------------------------------------------------------------------
// Kernel 2a: GEMM1 split-K partials, re-tiled for occupancy.
// grid (8 t-tiles, 4 k-slices, B) = 256 CTAs, 256 threads, smem ~33 KiB.
// Each CTA: out 64o x 64t, K=128 (two 64-d chunks). Thread: 4o x 4t.
// ---------------------------------------------------------------------------
__global__ void __launch_bounds__(256) gemm1_kernel(const float* __restrict__ w1) {
    __shared__ __align__(16) float Ps[64 * 64];      // [d][t] 16 KiB
    __shared__ __align__(16) float Ws[64 * 65 + 4];  // [o][d] padded

    int tid = threadIdx.x;
    int t0 = blockIdx.x * 64;
    int k0 = blockIdx.y * 128;
    int b  = blockIdx.z;
    int tq = tid & 15;          // t quad -> t = tq*4..tq*4+3
    int og = tid >> 4;          // 0..15  -> o = og*4..og*4+3

    float acc[4][4];
    #pragma unroll
    for (int o = 0; o < 4; o++)
        #pragma unroll
        for (int q = 0; q < 4; q++) acc[o][q] = 0.f;

    for (int c = 0; c < 2; c++) {
        int kc = k0 + c * 64;
        #pragma unroll
        for (int i = tid; i < 64 * 64; i += 256) {
            int d = i >> 6, t = i & 63;
            Ps[i] = g_pooled[((size_t)(b * D) + kc + d) * TC + t0 + t];
        }
        #pragma unroll
        for (int i = tid; i < 64 * 64; i += 256) {
            int o = i >> 6, d = i & 63;
            Ws[o * 65 + d] = w1[o * D + kc + d];
        }
        __syncthreads();

        #pragma unroll 8
        for (int dd = 0; dd < 64; dd++) {
            float4 p = *reinterpret_cast<const float4*>(&Ps[dd * 64 + tq * 4]);
            #pragma unroll
            for (int o = 0; o < 4; o++) {
                float w = Ws[(og * 4 + o) * 65 + dd];
                acc[o][0] = fmaf(w, p.x, acc[o][0]);
                acc[o][1] = fmaf(w, p.y, acc[o][1]);
                acc[o][2] = fmaf(w, p.z, acc[o][2]);
                acc[o][3] = fmaf(w, p.w, acc[o][3]);
            }
        }
        __syncthreads();
    }

    float* hp = g_hpart[blockIdx.y];
    #pragma unroll
    for (int o = 0; o < 4; o++) {
        float4 v = make_float4(acc[o][0], acc[o][1], acc[o][2], acc[o][3]);
        *reinterpret_cast<float4*>(
            &hp[((size_t)(b * DH) + og * 4 + o) * TC + t0 + tq * 4]) = v;
    }
}

// ---------------------------------------------------------------------------
// Kernel 2b: reduce 4 split-K partials + b1 + relu (fused into Hs load), then
// g[b,o,t] = sigmoid(sum_k w2[o,k]*h[b,k,t] + b2[o]).
// grid (8 t-tiles, 8 o-tiles, B) = 512 CTAs, 256 threads, smem ~33 KiB.
// ---------------------------------------------------------------------------
__global__ void __launch_bounds__(256) gemm2_kernel(
        const float* __restrict__ w2,
        const float* __restrict__ b1,
        const float* __restrict__ b2) {
    __shared__ __align__(16) float Hs[64 * 64];      // [k][t] 16 KiB
    __shared__ __align__(16) float Ws[64 * 65 + 4];  // [o][k] padded

    int tid = threadIdx.x;
    int t0 = blockIdx.x * 64;
    int o0 = blockIdx.y * 64;
    int b  = blockIdx.z;
    int tq = tid & 15;
    int og = tid >> 4;

    #pragma unroll
    for (int i = tid; i < 64 * 64; i += 256) {
        int k = i >> 6, t = i & 63;
        size_t idx = ((size_t)(b * DH) + k) * TC + t0 + t;
        float v = g_hpart[0][idx] + g_hpart[1][idx]
                + g_hpart[2][idx] + g_hpart[3][idx] + b1[k];
        Hs[i] = fmaxf(v, 0.f);
    }
    #pragma unroll
    for (int i = tid; i < 64 * 64; i += 256) {
        int o = i >> 6, k = i & 63;
        Ws[o * 65 + k] = w2[(o0 + o) * DH + k];
    }
    __syncthreads();

    float acc[4][4];
    #pragma unroll
    for (int o = 0; o < 4; o++)
        #pragma unroll
        for (int q = 0; q < 4; q++) acc[o][q] = 0.f;

    #pragma unroll 8
    for (int k = 0; k < 64; k++) {
        float4 h = *reinterpret_cast<const float4*>(&Hs[k * 64 + tq * 4]);
        #pragma unroll
        for (int o = 0; o < 4; o++) {
            float w = Ws[(og * 4 + o) * 65 + k];
            acc[o][0] = fmaf(w, h.x, acc[o][0]);
            acc[o][1] = fmaf(w, h.y, acc[o][1]);
            acc[o][2] = fmaf(w, h.z, acc[o][2]);
            acc[o][3] = fmaf(w, h.w, acc[o][3]);
        }
    }

    #pragma unroll
    for (int o = 0; o < 4; o++) {
        int oo = o0 + og * 4 + o;
        float bb = b2[oo];
        float4 g;
        g.x = 1.f / (1.f + __expf(-(acc[o][0] + bb)));
        g.y = 1.f / (1.f + __expf(-(acc[o][1] + bb)));
        g.z = 1.f / (1.f + __expf(-(acc[o][2] + bb)));
        g.w = 1.f / (1.f + __expf(-(acc[o][3] + bb)));
        *reinterpret_cast<float4*>(
            &g_gate[((size_t)(b * D) + oo) * TC + t0 + tq * 4]) = g;
    }
}

// ---------------------------------------------------------------------------
// Kernel 3: out = repeat(g,16) * x. Coalesced float4, 4-way ILP, streaming x.
// Measured 37.5 us (~DRAM floor).
// ---------------------------------------------------------------------------
__global__ void scale_kernel(const float* __restrict__ x, float* __restrict__ out) {
    const float4* x4 = reinterpret_cast<const float4*>(x);
    float4* o4 = reinterpret_cast<float4*>(out);
    size_t base = (size_t)blockIdx.x * blockDim.x + threadIdx.x;
    const size_t stride = (size_t)gridDim.x * blockDim.x;

    float4 xv[4];
    float  g[4];
    #pragma unroll
    for (int k = 0; k < 4; k++) {
        size_t i = base + (size_t)k * stride;
        xv[k] = __ldcs(&x4[i]);
    }
    #pragma unroll
    for (int k = 0; k < 4; k++) {
        size_t i = base + (size_t)k * stride;
        size_t row = i >> 11;               // / (T/4)
        size_t c   = (i & 2047) >> 2;       // chunk index
        g[k] = g_gate[row * TC + c];
    }
    #pragma unroll
    for (int k = 0; k < 4; k++) {
        size_t i = base + (size_t)k * stride;
        o4[i] = make_float4(xv[k].x * g[k], xv[k].y * g[k],
                            xv[k].z * g[k], xv[k].w * g[k]);
    }
}

// ---------------------------------------------------------------------------
extern "C" void kernel_launch(void* const* d_in, const int* in_sizes, int n_in,
                              void* d_out, int out_size) {
    const float* x  = (const float*)d_in[0];
    const float* w1 = (const float*)d_in[1];
    const float* b1 = (const float*)d_in[2];
    const float* w2 = (const float*)d_in[3];
    const float* b2 = (const float*)d_in[4];
    float* out = (float*)d_out;

    pool_kernel<<<B * D, 512>>>(x);
    gemm1_kernel<<<dim3(8, 4, B), 256>>>(w1);
    gemm2_kernel<<<dim3(8, 8, B), 256>>>(w2, b1, b2);
    scale_kernel<<<8192, 256>>>(x, out);
}

// round 6
// speedup vs baseline: 1.4592x; 1.0114x over previous
#include <cuda_runtime.h>

#define B  8
#define D  512
#define T  8192
#define CS 16
#define TC 512   // T / CS
#define DH 64    // D / 8

// Scratch (no cudaMalloc allowed)
__device__ float g_pooled[B * D * TC];          // 8 MiB
__device__ float g_hpart[4][B * DH * TC];       // 1 MiB per split-K slice

// ---------------------------------------------------------------------------
// Kernel 1: per (b,d) row — chunk sums of 16, inclusive scan, divide by count.
// Coalesced block-stride float4 streaming loads, lane-group-of-4 reduction,
// 512-wide block scan. Measured 24 us (~achievable DRAM ceiling).
// ---------------------------------------------------------------------------
__global__ void pool_kernel(const float* __restrict__ x) {
    int row = blockIdx.x;                      // b*D + d
    const float4* xr = reinterpret_cast<const float4*>(x) + (size_t)row * (T / 4);
    int j = threadIdx.x;

    __shared__ float csum[TC];
    __shared__ float wsum[16];

    float4 f0 = __ldcs(&xr[j]);
    float4 f1 = __ldcs(&xr[j + 512]);
    float4 f2 = __ldcs(&xr[j + 1024]);
    float4 f3 = __ldcs(&xr[j + 1536]);

    float s0 = (f0.x + f0.y) + (f0.z + f0.w);
    float s1 = (f1.x + f1.y) + (f1.z + f1.w);
    float s2 = (f2.x + f2.y) + (f2.z + f2.w);
    float s3 = (f3.x + f3.y) + (f3.z + f3.w);

    s0 += __shfl_xor_sync(0xffffffffu, s0, 1);
    s0 += __shfl_xor_sync(0xffffffffu, s0, 2);
    s1 += __shfl_xor_sync(0xffffffffu, s1, 1);
    s1 += __shfl_xor_sync(0xffffffffu, s1, 2);
    s2 += __shfl_xor_sync(0xffffffffu, s2, 1);
    s2 += __shfl_xor_sync(0xffffffffu, s2, 2);
    s3 += __shfl_xor_sync(0xffffffffu, s3, 1);
    s3 += __shfl_xor_sync(0xffffffffu, s3, 2);

    if ((j & 3) == 0) {
        int c = j >> 2;
        csum[c +   0] = s0;
        csum[c + 128] = s1;
        csum[c + 256] = s2;
        csum[c + 384] = s3;
    }
    __syncthreads();

    int lane = j & 31, warp = j >> 5;
    float v = csum[j];
    #pragma unroll
    for (int off = 1; off < 32; off <<= 1) {
        float n = __shfl_up_sync(0xffffffffu, v, off);
        if (lane >= off) v += n;
    }
    if (lane == 31) wsum[warp] = v;
    __syncthreads();
    if (warp == 0) {
        float w = (lane < 16) ? wsum[lane] : 0.f;
        #pragma unroll
        for (int off = 1; off < 16; off <<= 1) {
            float n = __shfl_up_sync(0xffffffffu, w, off);
            if (lane >= off) w += n;
        }
        if (lane < 16) wsum[lane] = w;
    }
    __syncthreads();

    float prefix = (warp > 0) ? wsum[warp - 1] : 0.f;
    float total  = v + prefix;
    g_pooled[(size_t)row * TC + j] = total / (float)(CS * (j + 1));
}

// ---------------------------------------------------------------------------
// Kernel 2a: GEMM1 split-K partials (occupancy-tiled, measured good in R5).
// grid (8 t-tiles, 4 k-slices, B) = 256 CTAs, 256 threads, smem ~33 KiB.
// ---------------------------------------------------------------------------
__global__ void __launch_bounds__(256) gemm1_kernel(const float* __restrict__ w1) {
    __shared__ __align__(16) float Ps[64 * 64];      // [d][t] 16 KiB
    __shared__ __align__(16) float Ws[64 * 65 + 4];  // [o][d] padded

    int tid = threadIdx.x;
    int t0 = blockIdx.x * 64;
    int k0 = blockIdx.y * 128;
    int b  = blockIdx.z;
    int tq = tid & 15;          // t quad -> t = tq*4..tq*4+3
    int og = tid >> 4;          // 0..15  -> o = og*4..og*4+3

    float acc[4][4];
    #pragma unroll
    for (int o = 0; o < 4; o++)
        #pragma unroll
        for (int q = 0; q < 4; q++) acc[o][q] = 0.f;

    for (int c = 0; c < 2; c++) {
        int kc = k0 + c * 64;
        // float4 fills: 1024 float4s of pooled, 256 threads -> 4 each
        #pragma unroll
        for (int i = tid; i < 64 * 16; i += 256) {
            int d = i >> 4, t4 = i & 15;
            *reinterpret_cast<float4*>(&Ps[d * 64 + t4 * 4]) =
                *reinterpret_cast<const float4*>(
                    &g_pooled[((size_t)(b * D) + kc + d) * TC + t0 + t4 * 4]);
        }
        #pragma unroll
        for (int i = tid; i < 64 * 64; i += 256) {
            int o = i >> 6, d = i & 63;
            Ws[o * 65 + d] = w1[o * D + kc + d];
        }
        __syncthreads();

        #pragma unroll 8
        for (int dd = 0; dd < 64; dd++) {
            float4 p = *reinterpret_cast<const float4*>(&Ps[dd * 64 + tq * 4]);
            #pragma unroll
            for (int o = 0; o < 4; o++) {
                float w = Ws[(og * 4 + o) * 65 + dd];
                acc[o][0] = fmaf(w, p.x, acc[o][0]);
                acc[o][1] = fmaf(w, p.y, acc[o][1]);
                acc[o][2] = fmaf(w, p.z, acc[o][2]);
                acc[o][3] = fmaf(w, p.w, acc[o][3]);
            }
        }
        __syncthreads();
    }

    float* hp = g_hpart[blockIdx.y];
    #pragma unroll
    for (int o = 0; o < 4; o++) {
        float4 v = make_float4(acc[o][0], acc[o][1], acc[o][2], acc[o][3]);
        *reinterpret_cast<float4*>(
            &hp[((size_t)(b * DH) + og * 4 + o) * TC + t0 + tq * 4]) = v;
    }
}

// ---------------------------------------------------------------------------
// Kernel 2b (FUSED): gemm2 + sigmoid gate + out = gate * x.
// Per CTA: b, o-tile 64 (gate rows = d dims of output), t-tile 64 chunks
// (= 1024 x columns). Grid (8,8,8) = 512 CTAs, 256 threads.
// Phase A: gate[64][64] = sigmoid(w2 @ relu(sum hpart + b1) + b2) -> smem
// Phase B: stream x region [64 rows x 1024 cols]: out = gate * x.
// ---------------------------------------------------------------------------
__global__ void __launch_bounds__(256) gate_scale_kernel(
        const float* __restrict__ w2,
        const float* __restrict__ b1,
        const float* __restrict__ b2,
        const float* __restrict__ x,
        float* __restrict__ out) {
    __shared__ __align__(16) float Hs[64 * 64];      // [k][t] then reused as gate [o][t]
    __shared__ __align__(16) float Ws[64 * 65 + 4];  // [o][k] padded

    int tid = threadIdx.x;
    int t0 = blockIdx.x * 64;        // pooled-chunk tile start
    int o0 = blockIdx.y * 64;        // gate/d row tile start
    int b  = blockIdx.z;
    int tq = tid & 15;
    int og = tid >> 4;

    // ---- Phase A1: load H (reduce split-K + b1 + relu) and W2 ----
    #pragma unroll
    for (int i = tid; i < 64 * 64; i += 256) {
        int k = i >> 6, t = i & 63;
        size_t idx = ((size_t)(b * DH) + k) * TC + t0 + t;
        float v = g_hpart[0][idx] + g_hpart[1][idx]
                + g_hpart[2][idx] + g_hpart[3][idx] + b1[k];
        Hs[i] = fmaxf(v, 0.f);
    }
    #pragma unroll
    for (int i = tid; i < 64 * 64; i += 256) {
        int o = i >> 6, k = i & 63;
        Ws[o * 65 + k] = w2[(o0 + o) * DH + k];
    }
    __syncthreads();

    // ---- Phase A2: GEMM 64o x 64t, K=64 ----
    float acc[4][4];
    #pragma unroll
    for (int o = 0; o < 4; o++)
        #pragma unroll
        for (int q = 0; q < 4; q++) acc[o][q] = 0.f;

    #pragma unroll 8
    for (int k = 0; k < 64; k++) {
        float4 h = *reinterpret_cast<const float4*>(&Hs[k * 64 + tq * 4]);
        #pragma unroll
        for (int o = 0; o < 4; o++) {
            float w = Ws[(og * 4 + o) * 65 + k];
            acc[o][0] = fmaf(w, h.x, acc[o][0]);
            acc[o][1] = fmaf(w, h.y, acc[o][1]);
            acc[o][2] = fmaf(w, h.z, acc[o][2]);
            acc[o][3] = fmaf(w, h.w, acc[o][3]);
        }
    }
    __syncthreads();   // Hs reads done; safe to overwrite with gate

    // ---- Phase A3: sigmoid -> gate tile in smem (Hs reused: [o_local][t]) ----
    #pragma unroll
    for (int o = 0; o < 4; o++) {
        float bb = b2[o0 + og * 4 + o];
        float4 g;
        g.x = 1.f / (1.f + __expf(-(acc[o][0] + bb)));
        g.y = 1.f / (1.f + __expf(-(acc[o][1] + bb)));
        g.z = 1.f / (1.f + __expf(-(acc[o][2] + bb)));
        g.w = 1.f / (1.f + __expf(-(acc[o][3] + bb)));
        *reinterpret_cast<float4*>(&Hs[(og * 4 + o) * 64 + tq * 4]) = g;
    }
    __syncthreads();

    // ---- Phase B: out = gate * x over [64 d-rows][1024 cols] ----
    // Warp w handles rows w*8 .. w*8+7; each row = 256 float4, 8 per lane.
    int warp = tid >> 5, lane = tid & 31;
    int c0 = t0 * CS;                         // starting x column (multiple of 1024)

    #pragma unroll
    for (int r = 0; r < 8; r++) {
        int o_local = warp * 8 + r;           // gate row / d offset
        size_t rowbase = ((size_t)(b * D) + o0 + o_local) * T + c0;
        const float4* xr = reinterpret_cast<const float4*>(x + rowbase);
        float4*       orp = reinterpret_cast<float4*>(out + rowbase);

        float4 xv[8];
        #pragma unroll
        for (int i = 0; i < 8; i++)
            xv[i] = __ldcs(&xr[i * 32 + lane]);

        float gv[8];
        #pragma unroll
        for (int i = 0; i < 8; i++)
            gv[i] = Hs[o_local * 64 + ((i * 32 + lane) >> 2)];

        #pragma unroll
        for (int i = 0; i < 8; i++)
            orp[i * 32 + lane] = make_float4(xv[i].x * gv[i], xv[i].y * gv[i],
                                             xv[i].z * gv[i], xv[i].w * gv[i]);
    }
}

// ---------------------------------------------------------------------------
extern "C" void kernel_launch(void* const* d_in, const int* in_sizes, int n_in,
                              void* d_out, int out_size) {
    const float* x  = (const float*)d_in[0];
    const float* w1 = (const float*)d_in[1];
    const float* b1 = (const float*)d_in[2];
    const float* w2 = (const float*)d_in[3];
    const float* b2 = (const float*)d_in[4];
    float* out = (float*)d_out;

    pool_kernel<<<B * D, 512>>>(x);
    gemm1_kernel<<<dim3(8, 4, B), 256>>>(w1);
    gate_scale_kernel<<<dim3(8, 8, B), 256>>>(w2, b1, b2, x, out);
}

// round 7
// speedup vs baseline: 1.5599x; 1.0690x over previous
#include <cuda_runtime.h>

#define B  8
#define D  512
#define T  8192
#define CS 16
#define TC 512   // T / CS
#define DH 64    // D / 8

// Scratch (no cudaMalloc allowed)
__device__ float g_pooled[B * D * TC];          // 8 MiB
__device__ float g_hpart[4][B * DH * TC];       // 1 MiB per split-K slice

// ---------------------------------------------------------------------------
// Kernel 1: per (b,d) row — chunk sums of 16, inclusive scan, divide by count.
// Coalesced block-stride float4 loads (CACHED: we want x resident in L2 for
// gate_scale), lane-group-of-4 reduction, 512-wide block scan.
// ---------------------------------------------------------------------------
__global__ void pool_kernel(const float* __restrict__ x) {
    int row = blockIdx.x;                      // b*D + d
    const float4* xr = reinterpret_cast<const float4*>(x) + (size_t)row * (T / 4);
    int j = threadIdx.x;

    __shared__ float csum[TC];
    __shared__ float wsum[16];

    float4 f0 = xr[j];
    float4 f1 = xr[j + 512];
    float4 f2 = xr[j + 1024];
    float4 f3 = xr[j + 1536];

    float s0 = (f0.x + f0.y) + (f0.z + f0.w);
    float s1 = (f1.x + f1.y) + (f1.z + f1.w);
    float s2 = (f2.x + f2.y) + (f2.z + f2.w);
    float s3 = (f3.x + f3.y) + (f3.z + f3.w);

    s0 += __shfl_xor_sync(0xffffffffu, s0, 1);
    s0 += __shfl_xor_sync(0xffffffffu, s0, 2);
    s1 += __shfl_xor_sync(0xffffffffu, s1, 1);
    s1 += __shfl_xor_sync(0xffffffffu, s1, 2);
    s2 += __shfl_xor_sync(0xffffffffu, s2, 1);
    s2 += __shfl_xor_sync(0xffffffffu, s2, 2);
    s3 += __shfl_xor_sync(0xffffffffu, s3, 1);
    s3 += __shfl_xor_sync(0xffffffffu, s3, 2);

    if ((j & 3) == 0) {
        int c = j >> 2;
        csum[c +   0] = s0;
        csum[c + 128] = s1;
        csum[c + 256] = s2;
        csum[c + 384] = s3;
    }
    __syncthreads();

    int lane = j & 31, warp = j >> 5;
    float v = csum[j];
    #pragma unroll
    for (int off = 1; off < 32; off <<= 1) {
        float n = __shfl_up_sync(0xffffffffu, v, off);
        if (lane >= off) v += n;
    }
    if (lane == 31) wsum[warp] = v;
    __syncthreads();
    if (warp == 0) {
        float w = (lane < 16) ? wsum[lane] : 0.f;
        #pragma unroll
        for (int off = 1; off < 16; off <<= 1) {
            float n = __shfl_up_sync(0xffffffffu, w, off);
            if (lane >= off) w += n;
        }
        if (lane < 16) wsum[lane] = w;
    }
    __syncthreads();

    float prefix = (warp > 0) ? wsum[warp - 1] : 0.f;
    float total  = v + prefix;
    g_pooled[(size_t)row * TC + j] = total / (float)(CS * (j + 1));
}

// ---------------------------------------------------------------------------
// Kernel 2a: GEMM1 split-K partials (occupancy-tiled).
// grid (8 t-tiles, 4 k-slices, B) = 256 CTAs, 256 threads, smem ~33 KiB.
// ---------------------------------------------------------------------------
__global__ void __launch_bounds__(256) gemm1_kernel(const float* __restrict__ w1) {
    __shared__ __align__(16) float Ps[64 * 64];      // [d][t] 16 KiB
    __shared__ __align__(16) float Ws[64 * 65 + 4];  // [o][d] padded

    int tid = threadIdx.x;
    int t0 = blockIdx.x * 64;
    int k0 = blockIdx.y * 128;
    int b  = blockIdx.z;
    int tq = tid & 15;          // t quad -> t = tq*4..tq*4+3
    int og = tid >> 4;          // 0..15  -> o = og*4..og*4+3

    float acc[4][4];
    #pragma unroll
    for (int o = 0; o < 4; o++)
        #pragma unroll
        for (int q = 0; q < 4; q++) acc[o][q] = 0.f;

    for (int c = 0; c < 2; c++) {
        int kc = k0 + c * 64;
        #pragma unroll
        for (int i = tid; i < 64 * 16; i += 256) {
            int d = i >> 4, t4 = i & 15;
            *reinterpret_cast<float4*>(&Ps[d * 64 + t4 * 4]) =
                *reinterpret_cast<const float4*>(
                    &g_pooled[((size_t)(b * D) + kc + d) * TC + t0 + t4 * 4]);
        }
        #pragma unroll
        for (int i = tid; i < 64 * 64; i += 256) {
            int o = i >> 6, d = i & 63;
            Ws[o * 65 + d] = w1[o * D + kc + d];
        }
        __syncthreads();

        #pragma unroll 8
        for (int dd = 0; dd < 64; dd++) {
            float4 p = *reinterpret_cast<const float4*>(&Ps[dd * 64 + tq * 4]);
            #pragma unroll
            for (int o = 0; o < 4; o++) {
                float w = Ws[(og * 4 + o) * 65 + dd];
                acc[o][0] = fmaf(w, p.x, acc[o][0]);
                acc[o][1] = fmaf(w, p.y, acc[o][1]);
                acc[o][2] = fmaf(w, p.z, acc[o][2]);
                acc[o][3] = fmaf(w, p.w, acc[o][3]);
            }
        }
        __syncthreads();
    }

    float* hp = g_hpart[blockIdx.y];
    #pragma unroll
    for (int o = 0; o < 4; o++) {
        float4 v = make_float4(acc[o][0], acc[o][1], acc[o][2], acc[o][3]);
        *reinterpret_cast<float4*>(
            &hp[((size_t)(b * DH) + og * 4 + o) * TC + t0 + tq * 4]) = v;
    }
}

// ---------------------------------------------------------------------------
// Kernel 2b (FUSED): gemm2 + sigmoid gate + out = gate * x.
// Per CTA: b (reversed for L2 LRU), o-tile 64, t-tile 64 chunks (1024 cols).
// Grid (8,8,8) = 512 CTAs, 256 threads.
// x reads CACHED (expected L2-resident from pool); out writes STREAMING
// (__stcs, evict-first) so they don't evict x.
// ---------------------------------------------------------------------------
__global__ void __launch_bounds__(256) gate_scale_kernel(
        const float* __restrict__ w2,
        const float* __restrict__ b1,
        const float* __restrict__ b2,
        const float* __restrict__ x,
        float* __restrict__ out) {
    __shared__ __align__(16) float Hs[64 * 64];      // [k][t] then gate [o][t]
    __shared__ __align__(16) float Ws[64 * 65 + 4];  // [o][k] padded

    int tid = threadIdx.x;
    int t0 = blockIdx.x * 64;            // pooled-chunk tile start
    int o0 = blockIdx.y * 64;            // gate/d row tile start
    int b  = (B - 1) - blockIdx.z;       // reversed: first CTAs hit freshest L2
    int tq = tid & 15;
    int og = tid >> 4;

    // ---- Phase A1: load H (reduce split-K + b1 + relu, float4) and W2 ----
    #pragma unroll
    for (int i = tid; i < 64 * 16; i += 256) {
        int k = i >> 4, t4 = i & 15;
        size_t idx = ((size_t)(b * DH) + k) * TC + t0 + t4 * 4;
        float4 a0 = *reinterpret_cast<const float4*>(&g_hpart[0][idx]);
        float4 a1 = *reinterpret_cast<const float4*>(&g_hpart[1][idx]);
        float4 a2 = *reinterpret_cast<const float4*>(&g_hpart[2][idx]);
        float4 a3 = *reinterpret_cast<const float4*>(&g_hpart[3][idx]);
        float bb = b1[k];
        float4 hv;
        hv.x = fmaxf(a0.x + a1.x + a2.x + a3.x + bb, 0.f);
        hv.y = fmaxf(a0.y + a1.y + a2.y + a3.y + bb, 0.f);
        hv.z = fmaxf(a0.z + a1.z + a2.z + a3.z + bb, 0.f);
        hv.w = fmaxf(a0.w + a1.w + a2.w + a3.w + bb, 0.f);
        *reinterpret_cast<float4*>(&Hs[k * 64 + t4 * 4]) = hv;
    }
    #pragma unroll
    for (int i = tid; i < 64 * 64; i += 256) {
        int o = i >> 6, k = i & 63;
        Ws[o * 65 + k] = w2[(o0 + o) * DH + k];
    }
    __syncthreads();

    // ---- Phase A2: GEMM 64o x 64t, K=64 ----
    float acc[4][4];
    #pragma unroll
    for (int o = 0; o < 4; o++)
        #pragma unroll
        for (int q = 0; q < 4; q++) acc[o][q] = 0.f;

    #pragma unroll 8
    for (int k = 0; k < 64; k++) {
        float4 h = *reinterpret_cast<const float4*>(&Hs[k * 64 + tq * 4]);
        #pragma unroll
        for (int o = 0; o < 4; o++) {
            float w = Ws[(og * 4 + o) * 65 + k];
            acc[o][0] = fmaf(w, h.x, acc[o][0]);
            acc[o][1] = fmaf(w, h.y, acc[o][1]);
            acc[o][2] = fmaf(w, h.z, acc[o][2]);
            acc[o][3] = fmaf(w, h.w, acc[o][3]);
        }
    }
    __syncthreads();   // Hs reads done; safe to overwrite with gate

    // ---- Phase A3: sigmoid -> gate tile in smem (Hs reused: [o_local][t]) ----
    #pragma unroll
    for (int o = 0; o < 4; o++) {
        float bb = b2[o0 + og * 4 + o];
        float4 g;
        g.x = 1.f / (1.f + __expf(-(acc[o][0] + bb)));
        g.y = 1.f / (1.f + __expf(-(acc[o][1] + bb)));
        g.z = 1.f / (1.f + __expf(-(acc[o][2] + bb)));
        g.w = 1.f / (1.f + __expf(-(acc[o][3] + bb)));
        *reinterpret_cast<float4*>(&Hs[(og * 4 + o) * 64 + tq * 4]) = g;
    }
    __syncthreads();

    // ---- Phase B: out = gate * x over [64 d-rows][1024 cols] ----
    int warp = tid >> 5, lane = tid & 31;
    int c0 = t0 * CS;                         // starting x column

    #pragma unroll
    for (int r = 0; r < 8; r++) {
        int o_local = warp * 8 + r;           // gate row / d offset
        size_t rowbase = ((size_t)(b * D) + o0 + o_local) * T + c0;
        const float4* xr = reinterpret_cast<const float4*>(x + rowbase);
        float4*       orp = reinterpret_cast<float4*>(out + rowbase);

        float4 xv[8];
        #pragma unroll
        for (int i = 0; i < 8; i++)
            xv[i] = xr[i * 32 + lane];        // cached — expect L2 hit

        float gv[8];
        #pragma unroll
        for (int i = 0; i < 8; i++)
            gv[i] = Hs[o_local * 64 + ((i * 32 + lane) >> 2)];

        #pragma unroll
        for (int i = 0; i < 8; i++) {
            float4 ov = make_float4(xv[i].x * gv[i], xv[i].y * gv[i],
                                    xv[i].z * gv[i], xv[i].w * gv[i]);
            __stcs(&orp[i * 32 + lane], ov);  // evict-first: protect x in L2
        }
    }
}

// ---------------------------------------------------------------------------
extern "C" void kernel_launch(void* const* d_in, const int* in_sizes, int n_in,
                              void* d_out, int out_size) {
    const float* x  = (const float*)d_in[0];
    const float* w1 = (const float*)d_in[1];
    const float* b1 = (const float*)d_in[2];
    const float* w2 = (const float*)d_in[3];
    const float* b2 = (const float*)d_in[4];
    float* out = (float*)d_out;

    pool_kernel<<<B * D, 512>>>(x);
    gemm1_kernel<<<dim3(8, 4, B), 256>>>(w1);
    gate_scale_kernel<<<dim3(8, 8, B), 256>>>(w2, b1, b2, x, out);
}